// round 5
// baseline (speedup 1.0000x reference)
#include <cuda_runtime.h>
#include <cuda_bf16.h>
#include <math.h>
#include <stdint.h>

#define DD 1024
#define BSZ 256

// ---- scratch globals --------------------------------------------------------
__device__ float g_h[BSZ * DD];
__device__ float g_logits[BSZ * DD];
__device__ float g_text2[BSZ * DD];
__device__ __nv_bfloat16 g_pretxt_h[BSZ * DD];
__device__ __nv_bfloat16 g_pimgb_h[BSZ * DD];
__device__ __nv_bfloat16 g_rw2_h[DD * DD];   // rw2 bf16, [k][n]

// ---- cp.async helpers ------------------------------------------------------
#define CP_ASYNC16(dst, src) \
    asm volatile("cp.async.cg.shared.global [%0], [%1], 16;" \
        :: "r"(dst), "l"(src) : "memory")
#define CP_COMMIT() asm volatile("cp.async.commit_group;" ::: "memory")
#define CP_WAIT0()  asm volatile("cp.async.wait_group 0;" ::: "memory")

// ============================================================================
// Small-chain fp32 GEMMs: 32x64 tile (128 CTAs -> more SM parallelism),
// BK=32, double-buffered, register prefetch, one __syncthreads per chunk.
// ============================================================================
template <bool RELU, bool HAS_BIAS, bool BF16OUT>
__device__ __forceinline__ void gemm32x64_body(
    const float* __restrict__ A, const float* __restrict__ B,
    const float* __restrict__ bias, void* __restrict__ Cv)
{
    __shared__ float As[2][32][36];   // [k][m] transposed, padded
    __shared__ float Bs[2][32][64];   // [k][n]

    const int t  = threadIdx.x;
    const int m0 = blockIdx.y * 32;
    const int n0 = blockIdx.x * 64;
    const int tx = t & 15, ty = t >> 4;

    // A loader: row = t>>3 (0..31), k-vec = (t&7)*4
    const int arr = t >> 3;
    const int akv = (t & 7) * 4;
    // B loader: k row = t>>3 (0..31), n-vec = (t&7)*8 (two float4)
    const int bkr = t >> 3;
    const int bnv = (t & 7) * 8;

    const float* Arow = A + (size_t)(m0 + arr) * DD + akv;
    const float* Brow = B + (size_t)bkr * DD + n0 + bnv;

    float4 a4, b0, b1;
    a4 = *(const float4*)(Arow);
    b0 = *(const float4*)(Brow);
    b1 = *(const float4*)(Brow + 4);
    As[0][akv + 0][arr] = a4.x; As[0][akv + 1][arr] = a4.y;
    As[0][akv + 2][arr] = a4.z; As[0][akv + 3][arr] = a4.w;
    *(float4*)(&Bs[0][bkr][bnv])     = b0;
    *(float4*)(&Bs[0][bkr][bnv + 4]) = b1;
    __syncthreads();

    float acc[2][4] = {};

    for (int c = 0; c < 32; c++) {
        const int s = c & 1;
        const int kn = (c + 1) * 32;

        if (c < 31) {
            a4 = *(const float4*)(Arow + kn);
            b0 = *(const float4*)(Brow + (size_t)kn * DD);
            b1 = *(const float4*)(Brow + (size_t)kn * DD + 4);
        }

        #pragma unroll
        for (int kk = 0; kk < 32; kk++) {
            float a[2], b[4];
            *(float2*)a = *(const float2*)(&As[s][kk][ty * 2]);
            *(float4*)b = *(const float4*)(&Bs[s][kk][tx * 4]);
            #pragma unroll
            for (int r = 0; r < 2; r++)
                #pragma unroll
                for (int cc = 0; cc < 4; cc++)
                    acc[r][cc] = fmaf(a[r], b[cc], acc[r][cc]);
        }

        if (c < 31) {
            const int ns = s ^ 1;
            As[ns][akv + 0][arr] = a4.x; As[ns][akv + 1][arr] = a4.y;
            As[ns][akv + 2][arr] = a4.z; As[ns][akv + 3][arr] = a4.w;
            *(float4*)(&Bs[ns][bkr][bnv])     = b0;
            *(float4*)(&Bs[ns][bkr][bnv + 4]) = b1;
        }
        __syncthreads();
    }

    #pragma unroll
    for (int r = 0; r < 2; r++) {
        const int m = m0 + ty * 2 + r;
        #pragma unroll
        for (int cc = 0; cc < 4; cc++) {
            const int n = n0 + tx * 4 + cc;
            float v = acc[r][cc];
            if (HAS_BIAS) v += bias[n];
            if (RELU) v = fmaxf(v, 0.0f);
            if (BF16OUT)
                ((__nv_bfloat16*)Cv)[(size_t)m * DD + n] = __float2bfloat16(v);
            else
                ((float*)Cv)[(size_t)m * DD + n] = v;
        }
    }
}

__global__ void __launch_bounds__(256)
small_pair(const float* __restrict__ text, const float* __restrict__ aw1,
           const float* __restrict__ ab1, float* __restrict__ h,
           const float* __restrict__ image, const float* __restrict__ rw1,
           const float* __restrict__ rb1, __nv_bfloat16* __restrict__ pimgb)
{
    if (blockIdx.z == 0)
        gemm32x64_body<true, true, false>(text, aw1, ab1, h);
    else
        gemm32x64_body<false, true, true>(image, rw1, rb1, pimgb);
}

__global__ void __launch_bounds__(256)
small_logits(const float* __restrict__ h, const float* __restrict__ aw2,
             const float* __restrict__ ab2, float* __restrict__ logits)
{
    gemm32x64_body<false, true, false>(h, aw2, ab2, logits);
}

__global__ void __launch_bounds__(256)
small_pretxt(const float* __restrict__ text2, const float* __restrict__ rw1b,
             __nv_bfloat16* __restrict__ pretxt)
{
    gemm32x64_body<false, false, true>(text2, rw1b, nullptr, pretxt);
}

// ---------------------------------------------------------------------------
__global__ void __launch_bounds__(256)
convert_rw2(const float* __restrict__ in, __nv_bfloat16* __restrict__ out)
{
    const int idx = (blockIdx.x * 256 + threadIdx.x) * 4;
    float4 v = *(const float4*)(in + idx);
    __nv_bfloat16 o[4] = {
        __float2bfloat16(v.x), __float2bfloat16(v.y),
        __float2bfloat16(v.z), __float2bfloat16(v.w)};
    *(uint2*)(out + idx) = *(uint2*)o;
}

// ---------------------------------------------------------------------------
__global__ void __launch_bounds__(256)
softmax_mul(const float* __restrict__ logits, const float* __restrict__ text,
            float* __restrict__ out)
{
    const int row = blockIdx.x;
    const int t   = threadIdx.x;
    const float* l = logits + (size_t)row * DD;
    __shared__ float smax[8];
    __shared__ float ssum[8];

    float m = -1e30f;
    #pragma unroll
    for (int k = t; k < DD; k += 256) m = fmaxf(m, l[k]);
    #pragma unroll
    for (int o = 16; o > 0; o >>= 1)
        m = fmaxf(m, __shfl_xor_sync(0xffffffffu, m, o));
    if ((t & 31) == 0) smax[t >> 5] = m;
    __syncthreads();
    float rowmax = smax[0];
    #pragma unroll
    for (int w = 1; w < 8; w++) rowmax = fmaxf(rowmax, smax[w]);

    float s = 0.0f;
    #pragma unroll
    for (int k = t; k < DD; k += 256) s += expf(l[k] - rowmax);
    #pragma unroll
    for (int o = 16; o > 0; o >>= 1)
        s += __shfl_xor_sync(0xffffffffu, s, o);
    if ((t & 31) == 0) ssum[t >> 5] = s;
    __syncthreads();
    float tot = 0.0f;
    #pragma unroll
    for (int w = 0; w < 8; w++) tot += ssum[w];
    const float inv = 1.0f / tot;

    const float* tr = text + (size_t)row * DD;
    float* orow = out + (size_t)row * DD;
    #pragma unroll
    for (int k = t; k < DD; k += 256)
        orow[k] = tr[k] * (expf(l[k] - rowmax) * inv);
}

// ============================================================================
// Big GEMM on mma.sync (bf16, fp32 accum).
// CTA tile 128x256, BK=32, 256 threads = 8 warps (2m x 4n), warp tile 64x64.
// Double-buffered SMEM; B via cp.async; A synthesized (relu(pretxt+pimgb)).
// SMEM (dynamic, 54272B):
//   A: [2][128][40] bf16 @ 0      (stage 10240B, row 80B)
//   B: [2][32][264]  bf16 @ 20480 (stage 16896B, row 528B)
// ============================================================================
#define LDSM_X4(r0,r1,r2,r3,addr) \
    asm volatile("ldmatrix.sync.aligned.m8n8.x4.shared.b16 {%0,%1,%2,%3}, [%4];" \
        : "=r"(r0),"=r"(r1),"=r"(r2),"=r"(r3) : "r"(addr))
#define LDSM_X4_T(r0,r1,r2,r3,addr) \
    asm volatile("ldmatrix.sync.aligned.m8n8.x4.trans.shared.b16 {%0,%1,%2,%3}, [%4];" \
        : "=r"(r0),"=r"(r1),"=r"(r2),"=r"(r3) : "r"(addr))
#define MMA_BF16(d0,d1,d2,d3,a0,a1,a2,a3,b0,b1) \
    asm volatile("mma.sync.aligned.m16n8k16.row.col.f32.bf16.bf16.f32 " \
        "{%0,%1,%2,%3}, {%4,%5,%6,%7}, {%8,%9}, {%0,%1,%2,%3};" \
        : "+f"(d0),"+f"(d1),"+f"(d2),"+f"(d3) \
        : "r"(a0),"r"(a1),"r"(a2),"r"(a3),"r"(b0),"r"(b1))

#define BIG_SMEM 54272

__device__ __forceinline__ uint4 fuse_relu_bf16(uint4 p, uint4 t)
{
    const __nv_bfloat162 z = __float2bfloat162_rn(0.0f);
    uint4 r;
    const __nv_bfloat162* pp = (const __nv_bfloat162*)&p;
    const __nv_bfloat162* tt = (const __nv_bfloat162*)&t;
    __nv_bfloat162* rr = (__nv_bfloat162*)&r;
    #pragma unroll
    for (int q = 0; q < 4; q++)
        rr[q] = __hmax2(__hadd2(pp[q], tt[q]), z);
    return r;
}

__global__ void __launch_bounds__(256, 1)
big_gemm_mma(const __nv_bfloat16* __restrict__ pretxt,
             const __nv_bfloat16* __restrict__ pimgb,
             const __nv_bfloat16* __restrict__ rw2,
             const float* __restrict__ image,
             const float* __restrict__ rb2,
             float* __restrict__ out)
{
    extern __shared__ char smem[];
    __nv_bfloat16* As0 = (__nv_bfloat16*)smem;             // [2][128][40]
    __nv_bfloat16* Bs0 = (__nv_bfloat16*)(smem + 20480);   // [2][32][264]

    const uint32_t ASTG = 10240;   // bytes per A stage
    const uint32_t BSTG = 16896;   // bytes per B stage

    const int t    = threadIdx.x;
    const int lane = t & 31;
    const int warp = t >> 5;
    const int n0 = blockIdx.x * 256;
    const int m0 = blockIdx.y * 128;
    const int i  = m0 >> 8;
    const int j0 = m0 & 255;

    const int wm = (warp >> 2) * 64;   // 0 or 64
    const int wn = (warp & 3) * 64;    // 0..192

    // loaders
    const int ar  = t >> 1;            // A row 0..127
    const int akv = (t & 1) * 16;      // 0 or 16
    const int br  = t >> 3;            // B k row 0..31
    const int bnv = (t & 7) * 32;      // 0..224 (4 x uint4 per thread)

    const __nv_bfloat16* ptrow = pretxt + (size_t)i * DD;
    const __nv_bfloat16* parow = pimgb + (size_t)(j0 + ar) * DD + akv;
    const __nv_bfloat16* pbrow = rw2 + (size_t)br * DD + n0 + bnv;

    const uint32_t bdst0 = (uint32_t)__cvta_generic_to_shared(
        Bs0 + br * 264 + bnv);

    const uint32_t aBase = (uint32_t)__cvta_generic_to_shared(
        As0 + (wm + ((lane >> 3) & 1) * 8 + (lane & 7)) * 40 + (lane >> 4) * 8);
    const uint32_t bBase = (uint32_t)__cvta_generic_to_shared(
        Bs0 + (((lane >> 3) & 1) * 8 + (lane & 7)) * 264 + wn + (lane >> 4) * 8);

    float acc[4][8][4] = {};   // [mt][nt][reg]

    // --- prologue: chunk 0 into stage 0 ---
    CP_ASYNC16(bdst0,      pbrow);
    CP_ASYNC16(bdst0 + 16, pbrow + 8);
    CP_ASYNC16(bdst0 + 32, pbrow + 16);
    CP_ASYNC16(bdst0 + 48, pbrow + 24);
    CP_COMMIT();
    {
        uint4 pv0 = *(const uint4*)(parow);
        uint4 pv1 = *(const uint4*)(parow + 8);
        uint4 tv0 = *(const uint4*)(ptrow + akv);
        uint4 tv1 = *(const uint4*)(ptrow + akv + 8);
        *(uint4*)(As0 + ar * 40 + akv)     = fuse_relu_bf16(pv0, tv0);
        *(uint4*)(As0 + ar * 40 + akv + 8) = fuse_relu_bf16(pv1, tv1);
    }
    CP_WAIT0();
    __syncthreads();

    uint4 pv0, pv1, tv0, tv1;
    for (int c = 0; c < 32; c++) {
        const int s  = c & 1;
        const int ns = s ^ 1;
        const int kn = (c + 1) * 32;

        if (c < 31) {   // issue next-chunk loads; latency overlaps compute
            const __nv_bfloat16* bsrc = pbrow + (size_t)kn * DD;
            CP_ASYNC16(bdst0 + ns * BSTG,      bsrc);
            CP_ASYNC16(bdst0 + ns * BSTG + 16, bsrc + 8);
            CP_ASYNC16(bdst0 + ns * BSTG + 32, bsrc + 16);
            CP_ASYNC16(bdst0 + ns * BSTG + 48, bsrc + 24);
            CP_COMMIT();
            pv0 = *(const uint4*)(parow + kn);
            pv1 = *(const uint4*)(parow + kn + 8);
            tv0 = *(const uint4*)(ptrow + kn + akv);
            tv1 = *(const uint4*)(ptrow + kn + akv + 8);
        }

        // ---- compute on stage s ----
        const uint32_t aB = aBase + s * ASTG;
        const uint32_t bB = bBase + s * BSTG;
        #pragma unroll
        for (int ks = 0; ks < 2; ks++) {
            const int kk = ks * 16;
            unsigned a[4][4];
            #pragma unroll
            for (int mt = 0; mt < 4; mt++)
                LDSM_X4(a[mt][0], a[mt][1], a[mt][2], a[mt][3],
                        aB + mt * 16 * 80 + kk * 2);
            unsigned b[8][2];
            #pragma unroll
            for (int bt = 0; bt < 4; bt++)
                LDSM_X4_T(b[bt*2][0], b[bt*2][1], b[bt*2+1][0], b[bt*2+1][1],
                          bB + kk * 528 + bt * 32);
            #pragma unroll
            for (int mt = 0; mt < 4; mt++)
                #pragma unroll
                for (int nt = 0; nt < 8; nt++)
                    MMA_BF16(acc[mt][nt][0], acc[mt][nt][1],
                             acc[mt][nt][2], acc[mt][nt][3],
                             a[mt][0], a[mt][1], a[mt][2], a[mt][3],
                             b[nt][0], b[nt][1]);
        }

        if (c < 31) {   // store prefetched A into next stage; drain B cp.async
            *(uint4*)(As0 + ns * 5120 + ar * 40 + akv)     = fuse_relu_bf16(pv0, tv0);
            *(uint4*)(As0 + ns * 5120 + ar * 40 + akv + 8) = fuse_relu_bf16(pv1, tv1);
            CP_WAIT0();
        }
        __syncthreads();
    }

    // ---- epilogue: + image[j] + rb2 ----
    #pragma unroll
    for (int mt = 0; mt < 4; mt++) {
        const int rbase = wm + mt * 16 + (lane >> 2);
        #pragma unroll
        for (int half = 0; half < 2; half++) {
            const int r = rbase + half * 8;
            const float* img = image + (size_t)(j0 + r) * DD;
            const size_t orow = (size_t)(m0 + r) * DD;
            #pragma unroll
            for (int nt = 0; nt < 8; nt++) {
                const int col = n0 + wn + nt * 8 + (lane & 3) * 2;
                float2 im = *(const float2*)(img + col);
                float2 rb = *(const float2*)(rb2 + col);
                float2 o;
                o.x = acc[mt][nt][half * 2 + 0] + im.x + rb.x;
                o.y = acc[mt][nt][half * 2 + 1] + im.y + rb.y;
                *(float2*)(out + orow + col) = o;
            }
        }
    }
}

// ---------------------------------------------------------------------------
extern "C" void kernel_launch(void* const* d_in, const int* in_sizes, int n_in,
                              void* d_out, int out_size)
{
    const float* image = (const float*)d_in[0];
    const float* text  = (const float*)d_in[1];
    const float* aw1   = (const float*)d_in[2];
    const float* ab1   = (const float*)d_in[3];
    const float* aw2   = (const float*)d_in[4];
    const float* ab2   = (const float*)d_in[5];
    const float* rw1   = (const float*)d_in[6];
    const float* rb1   = (const float*)d_in[7];
    const float* rw2   = (const float*)d_in[8];
    const float* rb2   = (const float*)d_in[9];
    float* out = (float*)d_out;

    float *h_p, *logits_p, *text2_p;
    __nv_bfloat16 *pretxt_p, *pimgb_p, *rw2h_p;
    cudaGetSymbolAddress((void**)&h_p,      g_h);
    cudaGetSymbolAddress((void**)&logits_p, g_logits);
    cudaGetSymbolAddress((void**)&text2_p,  g_text2);
    cudaGetSymbolAddress((void**)&pretxt_p, g_pretxt_h);
    cudaGetSymbolAddress((void**)&pimgb_p,  g_pimgb_h);
    cudaGetSymbolAddress((void**)&rw2h_p,   g_rw2_h);

    // Deterministic, idempotent, host-side (not captured as graph work).
    cudaFuncSetAttribute(big_gemm_mma,
                         cudaFuncAttributeMaxDynamicSharedMemorySize, BIG_SMEM);

    dim3 blk(256);
    dim3 gsmall(16, 8);   // 32x64 tiles over [256 x 1024]

    // rw2 -> bf16 (independent of the chain)
    convert_rw2<<<DD * DD / 1024, blk>>>(rw2, rw2h_p);
    // z=0: h = relu(text@aw1+ab1); z=1: pimgb = bf16(image@rw1[:D]+rb1)
    small_pair<<<dim3(16, 8, 2), blk>>>(
        text, aw1, ab1, h_p, image, rw1, rb1, pimgb_p);
    // logits = h @ aw2 + ab2
    small_logits<<<gsmall, blk>>>(h_p, aw2, ab2, logits_p);
    // text2 = text * softmax(logits)
    softmax_mul<<<BSZ, blk>>>(logits_p, text, text2_p);
    // pretxt = bf16(text2 @ rw1[D:])
    small_pretxt<<<gsmall, blk>>>(text2_p, rw1 + (size_t)DD * DD, pretxt_p);
    // big fused GEMM on tensor cores (mma.sync), CTA tile 128x256
    big_gemm_mma<<<dim3(4, 512), blk, BIG_SMEM>>>(
        pretxt_p, pimgb_p, rw2h_p, image, rb2, out);
}

// round 6
// speedup vs baseline: 1.0994x; 1.0994x over previous
#include <cuda_runtime.h>
#include <cuda_bf16.h>
#include <math.h>
#include <stdint.h>

#define DD 1024
#define BSZ 256

// ---- scratch globals --------------------------------------------------------
__device__ float g_h[BSZ * DD];
__device__ float g_logits[BSZ * DD];
__device__ float g_text2[BSZ * DD];
__device__ __nv_bfloat16 g_pretxt_h[BSZ * DD];
__device__ __nv_bfloat16 g_pimgb_h[BSZ * DD];
__device__ __nv_bfloat16 g_rw2_h[DD * DD];   // rw2 bf16, [k][n]

// ---- cp.async helpers ------------------------------------------------------
#define CP_ASYNC16(dst, src) \
    asm volatile("cp.async.cg.shared.global [%0], [%1], 16;" \
        :: "r"(dst), "l"(src) : "memory")
#define CP_COMMIT() asm volatile("cp.async.commit_group;" ::: "memory")
#define CP_WAIT0()  asm volatile("cp.async.wait_group 0;" ::: "memory")

// ============================================================================
// Small-chain fp32 GEMMs (round-4 version — known good at 660us total):
// 64x64 tile, BK=32, double-buffered, register prefetch, one sync per chunk.
// ============================================================================
template <bool RELU, bool HAS_BIAS, bool BF16OUT>
__device__ __forceinline__ void gemm64_body(
    const float* __restrict__ A, const float* __restrict__ B,
    const float* __restrict__ bias, void* __restrict__ Cv, float* smem)
{
    const int AS  = 32 * 68;
    const int BS_ = 32 * 64;
    const int STG = AS + BS_;

    const int t  = threadIdx.x;
    const int m0 = blockIdx.y * 64;
    const int n0 = blockIdx.x * 64;
    const int tx = t & 15, ty = t >> 4;

    const int ar  = t & 63;
    const int akv = (t >> 6) * 8;
    const int bk  = t >> 3;
    const int bnv = (t & 7) * 8;

    const float* Arow = A + (size_t)(m0 + ar) * DD + akv;
    const float* Brow = B + (size_t)bk * DD + n0 + bnv;

    float4 a0, a1, b0, b1;
    a0 = *(const float4*)(Arow);
    a1 = *(const float4*)(Arow + 4);
    b0 = *(const float4*)(Brow);
    b1 = *(const float4*)(Brow + 4);
    {
        float* Ad = smem;
        float* Bd = smem + AS;
        Ad[(akv + 0) * 68 + ar] = a0.x; Ad[(akv + 1) * 68 + ar] = a0.y;
        Ad[(akv + 2) * 68 + ar] = a0.z; Ad[(akv + 3) * 68 + ar] = a0.w;
        Ad[(akv + 4) * 68 + ar] = a1.x; Ad[(akv + 5) * 68 + ar] = a1.y;
        Ad[(akv + 6) * 68 + ar] = a1.z; Ad[(akv + 7) * 68 + ar] = a1.w;
        *(float4*)(&Bd[bk * 64 + bnv])     = b0;
        *(float4*)(&Bd[bk * 64 + bnv + 4]) = b1;
    }
    __syncthreads();

    float acc[4][4] = {};

    for (int c = 0; c < 32; c++) {
        const int s = c & 1;
        const float* As = smem + s * STG;
        const float* Bs = smem + s * STG + AS;
        const int kn = (c + 1) * 32;

        if (c < 31) {
            a0 = *(const float4*)(Arow + kn);
            a1 = *(const float4*)(Arow + kn + 4);
            b0 = *(const float4*)(Brow + (size_t)kn * DD);
            b1 = *(const float4*)(Brow + (size_t)kn * DD + 4);
        }

        #pragma unroll
        for (int kk = 0; kk < 32; kk++) {
            float a[4], b[4];
            *(float4*)a = *(const float4*)(&As[kk * 68 + ty * 4]);
            *(float4*)b = *(const float4*)(&Bs[kk * 64 + tx * 4]);
            #pragma unroll
            for (int r = 0; r < 4; r++)
                #pragma unroll
                for (int cc = 0; cc < 4; cc++)
                    acc[r][cc] = fmaf(a[r], b[cc], acc[r][cc]);
        }

        if (c < 31) {
            float* Ad = smem + (s ^ 1) * STG;
            float* Bd = Ad + AS;
            Ad[(akv + 0) * 68 + ar] = a0.x; Ad[(akv + 1) * 68 + ar] = a0.y;
            Ad[(akv + 2) * 68 + ar] = a0.z; Ad[(akv + 3) * 68 + ar] = a0.w;
            Ad[(akv + 4) * 68 + ar] = a1.x; Ad[(akv + 5) * 68 + ar] = a1.y;
            Ad[(akv + 6) * 68 + ar] = a1.z; Ad[(akv + 7) * 68 + ar] = a1.w;
            *(float4*)(&Bd[bk * 64 + bnv])     = b0;
            *(float4*)(&Bd[bk * 64 + bnv + 4]) = b1;
        }
        __syncthreads();
    }

    #pragma unroll
    for (int r = 0; r < 4; r++) {
        const int m = m0 + ty * 4 + r;
        #pragma unroll
        for (int c = 0; c < 4; c++) {
            const int n = n0 + tx * 4 + c;
            float v = acc[r][c];
            if (HAS_BIAS) v += bias[n];
            if (RELU) v = fmaxf(v, 0.0f);
            if (BF16OUT)
                ((__nv_bfloat16*)Cv)[(size_t)m * DD + n] = __float2bfloat16(v);
            else
                ((float*)Cv)[(size_t)m * DD + n] = v;
        }
    }
}

#define SMALL_SMEM (2 * (32 * 68 + 32 * 64) * (int)sizeof(float))

__global__ void __launch_bounds__(256)
small_pair(const float* __restrict__ text, const float* __restrict__ aw1,
           const float* __restrict__ ab1, float* __restrict__ h,
           const float* __restrict__ image, const float* __restrict__ rw1,
           const float* __restrict__ rb1, __nv_bfloat16* __restrict__ pimgb)
{
    extern __shared__ float smemf[];
    if (blockIdx.z == 0)
        gemm64_body<true, true, false>(text, aw1, ab1, h, smemf);
    else
        gemm64_body<false, true, true>(image, rw1, rb1, pimgb, smemf);
}

__global__ void __launch_bounds__(256)
small_logits(const float* __restrict__ h, const float* __restrict__ aw2,
             const float* __restrict__ ab2, float* __restrict__ logits)
{
    extern __shared__ float smemf[];
    gemm64_body<false, true, false>(h, aw2, ab2, logits, smemf);
}

__global__ void __launch_bounds__(256)
small_pretxt(const float* __restrict__ text2, const float* __restrict__ rw1b,
             __nv_bfloat16* __restrict__ pretxt)
{
    extern __shared__ float smemf[];
    gemm64_body<false, false, true>(text2, rw1b, nullptr, pretxt, smemf);
}

// ---------------------------------------------------------------------------
__global__ void __launch_bounds__(256)
convert_rw2(const float* __restrict__ in, __nv_bfloat16* __restrict__ out)
{
    const int idx = (blockIdx.x * 256 + threadIdx.x) * 4;
    float4 v = *(const float4*)(in + idx);
    __nv_bfloat16 o[4] = {
        __float2bfloat16(v.x), __float2bfloat16(v.y),
        __float2bfloat16(v.z), __float2bfloat16(v.w)};
    *(uint2*)(out + idx) = *(uint2*)o;
}

// ---------------------------------------------------------------------------
__global__ void __launch_bounds__(256)
softmax_mul(const float* __restrict__ logits, const float* __restrict__ text,
            float* __restrict__ out)
{
    const int row = blockIdx.x;
    const int t   = threadIdx.x;
    const float* l = logits + (size_t)row * DD;
    __shared__ float smax[8];
    __shared__ float ssum[8];

    float m = -1e30f;
    #pragma unroll
    for (int k = t; k < DD; k += 256) m = fmaxf(m, l[k]);
    #pragma unroll
    for (int o = 16; o > 0; o >>= 1)
        m = fmaxf(m, __shfl_xor_sync(0xffffffffu, m, o));
    if ((t & 31) == 0) smax[t >> 5] = m;
    __syncthreads();
    float rowmax = smax[0];
    #pragma unroll
    for (int w = 1; w < 8; w++) rowmax = fmaxf(rowmax, smax[w]);

    float s = 0.0f;
    #pragma unroll
    for (int k = t; k < DD; k += 256) s += expf(l[k] - rowmax);
    #pragma unroll
    for (int o = 16; o > 0; o >>= 1)
        s += __shfl_xor_sync(0xffffffffu, s, o);
    if ((t & 31) == 0) ssum[t >> 5] = s;
    __syncthreads();
    float tot = 0.0f;
    #pragma unroll
    for (int w = 0; w < 8; w++) tot += ssum[w];
    const float inv = 1.0f / tot;

    const float* tr = text + (size_t)row * DD;
    float* orow = out + (size_t)row * DD;
    #pragma unroll
    for (int k = t; k < DD; k += 256)
        orow[k] = tr[k] * (expf(l[k] - rowmax) * inv);
}

// ============================================================================
// Big GEMM on mma.sync (bf16, fp32 accum).
// CTA tile 128x128, BK=64, 256 threads = 8 warps (2m x 4n), warp tile 64x32.
// 2 CTAs/SM. Double-buffered SMEM; B via cp.async; A synthesized
// relu(pretxt+pimgb) with pretxt staged in SMEM (register budget).
// Dynamic SMEM 73728B:
//   A: [2][128][72] bf16 @ 0       (stage 18432B, row 144B -> LDSM rotates banks)
//   B: [2][64][136] bf16 @ 36864   (stage 17408B, row 272B)
//   pretxt row: 1024 bf16 @ 71680  (2048B)
// ============================================================================
#define LDSM_X4(r0,r1,r2,r3,addr) \
    asm volatile("ldmatrix.sync.aligned.m8n8.x4.shared.b16 {%0,%1,%2,%3}, [%4];" \
        : "=r"(r0),"=r"(r1),"=r"(r2),"=r"(r3) : "r"(addr))
#define LDSM_X4_T(r0,r1,r2,r3,addr) \
    asm volatile("ldmatrix.sync.aligned.m8n8.x4.trans.shared.b16 {%0,%1,%2,%3}, [%4];" \
        : "=r"(r0),"=r"(r1),"=r"(r2),"=r"(r3) : "r"(addr))
#define MMA_BF16(d0,d1,d2,d3,a0,a1,a2,a3,b0,b1) \
    asm volatile("mma.sync.aligned.m16n8k16.row.col.f32.bf16.bf16.f32 " \
        "{%0,%1,%2,%3}, {%4,%5,%6,%7}, {%8,%9}, {%0,%1,%2,%3};" \
        : "+f"(d0),"+f"(d1),"+f"(d2),"+f"(d3) \
        : "r"(a0),"r"(a1),"r"(a2),"r"(a3),"r"(b0),"r"(b1))

#define BIG_SMEM 73728

__device__ __forceinline__ uint4 fuse_relu_bf16(uint4 p, uint4 t)
{
    const __nv_bfloat162 z = __float2bfloat162_rn(0.0f);
    uint4 r;
    const __nv_bfloat162* pp = (const __nv_bfloat162*)&p;
    const __nv_bfloat162* tt = (const __nv_bfloat162*)&t;
    __nv_bfloat162* rr = (__nv_bfloat162*)&r;
    #pragma unroll
    for (int q = 0; q < 4; q++)
        rr[q] = __hmax2(__hadd2(pp[q], tt[q]), z);
    return r;
}

__global__ void __launch_bounds__(256, 2)
big_gemm_mma(const __nv_bfloat16* __restrict__ pretxt,
             const __nv_bfloat16* __restrict__ pimgb,
             const __nv_bfloat16* __restrict__ rw2,
             const float* __restrict__ image,
             const float* __restrict__ rb2,
             float* __restrict__ out)
{
    extern __shared__ char smem[];
    __nv_bfloat16* As0  = (__nv_bfloat16*)smem;              // [2][128][72]
    __nv_bfloat16* Bs0  = (__nv_bfloat16*)(smem + 36864);    // [2][64][136]
    __nv_bfloat16* ptxs = (__nv_bfloat16*)(smem + 71680);    // [1024]

    const uint32_t ASTG  = 18432;   // bytes per A stage
    const uint32_t ASTGE = 9216;    // elements per A stage
    const uint32_t BSTG  = 17408;   // bytes per B stage

    const int t    = threadIdx.x;
    const int lane = t & 31;
    const int warp = t >> 5;
    const int n0 = blockIdx.x * 128;
    const int m0 = blockIdx.y * 128;
    const int i  = m0 >> 8;
    const int j0 = m0 & 255;

    const int wm = (warp >> 2) * 64;   // 0 or 64
    const int wn = (warp & 3) * 32;    // 0..96

    // loaders (per chunk of 64 k)
    const int ar  = t >> 1;            // A row 0..127
    const int akv = (t & 1) * 32;      // 0 or 32 (elems)
    const int br  = t >> 2;            // B k row 0..63
    const int bnv = (t & 3) * 32;      // 0..96 (elems)

    const __nv_bfloat16* ptrow = pretxt + (size_t)i * DD;
    const __nv_bfloat16* parow = pimgb + (size_t)(j0 + ar) * DD + akv;
    const __nv_bfloat16* pbrow = rw2 + (size_t)br * DD + n0 + bnv;

    const uint32_t bdst0 = (uint32_t)__cvta_generic_to_shared(
        Bs0 + br * 136 + bnv);

    const uint32_t aBase = (uint32_t)__cvta_generic_to_shared(As0)
        + (wm + ((lane >> 3) & 1) * 8 + (lane & 7)) * 144 + (lane >> 4) * 16;
    const uint32_t bBase = (uint32_t)__cvta_generic_to_shared(Bs0)
        + (((lane >> 3) & 1) * 8 + (lane & 7)) * 272 + (wn + (lane >> 4) * 8) * 2;

    float acc[4][4][4] = {};   // [mt][nt][reg]

    // --- prologue ---
    // stage pretxt row into SMEM (one uint2 = 4 bf16 per thread)
    *(uint2*)(ptxs + t * 4) = *(const uint2*)(ptrow + t * 4);
    // chunk 0: B via cp.async
    CP_ASYNC16(bdst0,      pbrow);
    CP_ASYNC16(bdst0 + 16, pbrow + 8);
    CP_ASYNC16(bdst0 + 32, pbrow + 16);
    CP_ASYNC16(bdst0 + 48, pbrow + 24);
    CP_COMMIT();
    // chunk 0: A synthesized (pretxt straight from global here)
    {
        __nv_bfloat16* Ad = As0 + ar * 72 + akv;
        #pragma unroll
        for (int q = 0; q < 4; q++) {
            uint4 pv = *(const uint4*)(parow + q * 8);
            uint4 tv = *(const uint4*)(ptrow + akv + q * 8);
            *(uint4*)(Ad + q * 8) = fuse_relu_bf16(pv, tv);
        }
    }
    CP_WAIT0();
    __syncthreads();

    uint4 pv0, pv1, pv2, pv3;
    for (int c = 0; c < 16; c++) {
        const int s  = c & 1;
        const int ns = s ^ 1;
        const int kn = (c + 1) * 64;

        if (c < 15) {   // issue next-chunk loads; latency overlaps compute
            const __nv_bfloat16* bsrc = pbrow + (size_t)kn * DD;
            CP_ASYNC16(bdst0 + ns * BSTG,      bsrc);
            CP_ASYNC16(bdst0 + ns * BSTG + 16, bsrc + 8);
            CP_ASYNC16(bdst0 + ns * BSTG + 32, bsrc + 16);
            CP_ASYNC16(bdst0 + ns * BSTG + 48, bsrc + 24);
            CP_COMMIT();
            pv0 = *(const uint4*)(parow + kn);
            pv1 = *(const uint4*)(parow + kn + 8);
            pv2 = *(const uint4*)(parow + kn + 16);
            pv3 = *(const uint4*)(parow + kn + 24);
        }

        // ---- compute 4 k16 steps on stage s ----
        const uint32_t aB = aBase + s * ASTG;
        const uint32_t bB = bBase + s * BSTG;
        #pragma unroll
        for (int ks = 0; ks < 4; ks++) {
            const int kk = ks * 16;
            unsigned a[4][4];
            #pragma unroll
            for (int mt = 0; mt < 4; mt++)
                LDSM_X4(a[mt][0], a[mt][1], a[mt][2], a[mt][3],
                        aB + mt * 16 * 144 + kk * 2);
            unsigned b[4][2];
            #pragma unroll
            for (int bt = 0; bt < 2; bt++)
                LDSM_X4_T(b[bt*2][0], b[bt*2][1], b[bt*2+1][0], b[bt*2+1][1],
                          bB + kk * 272 + bt * 32);
            #pragma unroll
            for (int mt = 0; mt < 4; mt++)
                #pragma unroll
                for (int nt = 0; nt < 4; nt++)
                    MMA_BF16(acc[mt][nt][0], acc[mt][nt][1],
                             acc[mt][nt][2], acc[mt][nt][3],
                             a[mt][0], a[mt][1], a[mt][2], a[mt][3],
                             b[nt][0], b[nt][1]);
        }

        if (c < 15) {   // synthesize A into next stage (pretxt from SMEM)
            __nv_bfloat16* Ad = As0 + ns * ASTGE + ar * 72 + akv;
            const __nv_bfloat16* tp = ptxs + kn + akv;
            uint4 tv0 = *(const uint4*)(tp);
            uint4 tv1 = *(const uint4*)(tp + 8);
            uint4 tv2 = *(const uint4*)(tp + 16);
            uint4 tv3 = *(const uint4*)(tp + 24);
            *(uint4*)(Ad)      = fuse_relu_bf16(pv0, tv0);
            *(uint4*)(Ad + 8)  = fuse_relu_bf16(pv1, tv1);
            *(uint4*)(Ad + 16) = fuse_relu_bf16(pv2, tv2);
            *(uint4*)(Ad + 24) = fuse_relu_bf16(pv3, tv3);
            CP_WAIT0();
        }
        __syncthreads();
    }

    // ---- epilogue: + image[j] + rb2 ----
    #pragma unroll
    for (int mt = 0; mt < 4; mt++) {
        const int rbase = wm + mt * 16 + (lane >> 2);
        #pragma unroll
        for (int half = 0; half < 2; half++) {
            const int r = rbase + half * 8;
            const float* img = image + (size_t)(j0 + r) * DD;
            const size_t orow = (size_t)(m0 + r) * DD;
            #pragma unroll
            for (int nt = 0; nt < 4; nt++) {
                const int col = n0 + wn + nt * 8 + (lane & 3) * 2;
                float2 im = *(const float2*)(img + col);
                float2 rb = *(const float2*)(rb2 + col);
                float2 o;
                o.x = acc[mt][nt][half * 2 + 0] + im.x + rb.x;
                o.y = acc[mt][nt][half * 2 + 1] + im.y + rb.y;
                *(float2*)(out + orow + col) = o;
            }
        }
    }
}

// ---------------------------------------------------------------------------
extern "C" void kernel_launch(void* const* d_in, const int* in_sizes, int n_in,
                              void* d_out, int out_size)
{
    const float* image = (const float*)d_in[0];
    const float* text  = (const float*)d_in[1];
    const float* aw1   = (const float*)d_in[2];
    const float* ab1   = (const float*)d_in[3];
    const float* aw2   = (const float*)d_in[4];
    const float* ab2   = (const float*)d_in[5];
    const float* rw1   = (const float*)d_in[6];
    const float* rb1   = (const float*)d_in[7];
    const float* rw2   = (const float*)d_in[8];
    const float* rb2   = (const float*)d_in[9];
    float* out = (float*)d_out;

    float *h_p, *logits_p, *text2_p;
    __nv_bfloat16 *pretxt_p, *pimgb_p, *rw2h_p;
    cudaGetSymbolAddress((void**)&h_p,      g_h);
    cudaGetSymbolAddress((void**)&logits_p, g_logits);
    cudaGetSymbolAddress((void**)&text2_p,  g_text2);
    cudaGetSymbolAddress((void**)&pretxt_p, g_pretxt_h);
    cudaGetSymbolAddress((void**)&pimgb_p,  g_pimgb_h);
    cudaGetSymbolAddress((void**)&rw2h_p,   g_rw2_h);

    // Host-side attr set; deterministic & idempotent.
    cudaFuncSetAttribute(big_gemm_mma,
                         cudaFuncAttributeMaxDynamicSharedMemorySize, BIG_SMEM);

    dim3 blk(256);

    // rw2 -> bf16 (independent of the chain)
    convert_rw2<<<DD * DD / 1024, blk>>>(rw2, rw2h_p);
    // z=0: h = relu(text@aw1+ab1); z=1: pimgb = bf16(image@rw1[:D]+rb1)
    small_pair<<<dim3(16, 4, 2), blk, SMALL_SMEM>>>(
        text, aw1, ab1, h_p, image, rw1, rb1, pimgb_p);
    // logits = h @ aw2 + ab2
    small_logits<<<dim3(16, 4), blk, SMALL_SMEM>>>(h_p, aw2, ab2, logits_p);
    // text2 = text * softmax(logits)
    softmax_mul<<<BSZ, blk>>>(logits_p, text, text2_p);
    // pretxt = bf16(text2 @ rw1[D:])
    small_pretxt<<<dim3(16, 4), blk, SMALL_SMEM>>>(
        text2_p, rw1 + (size_t)DD * DD, pretxt_p);
    // big fused GEMM on tensor cores (mma.sync), BK=64
    big_gemm_mma<<<dim3(8, 512), blk, BIG_SMEM>>>(
        pretxt_p, pimgb_p, rw2h_p, image, rb2, out);
}